// round 10
// baseline (speedup 1.0000x reference)
#include <cuda_runtime.h>
#include <cuda_bf16.h>
#include <mma.h>
#include <cstdint>

using namespace nvcuda;

#define BB   16
#define UU   1024
#define HH   8
#define CC   128
#define SS   1024
#define SCALE 0.08838834764831843f   // 1/sqrt(128)

#define NMASK ((size_t)BB * SS * SS)

// ---------------------------------------------------------------------------
// Scratch
// ---------------------------------------------------------------------------
__device__ float g_qkv[(size_t)BB * 3 * UU * SS];
__device__ float g_coef[BB * SS];
__device__ unsigned char g_mask[NMASK];
__device__ int g_mode;
__device__ __nv_bfloat16 g_wq_h[(size_t)3 * UU * UU];
__device__ __nv_bfloat16 g_wq_l[(size_t)3 * UU * UU];
__device__ __nv_bfloat16 g_wo_h[(size_t)UU * UU];
__device__ __nv_bfloat16 g_wo_l[(size_t)UU * UU];
__device__ __nv_bfloat16 g_xt_h[(size_t)BB * UU * SS];
__device__ __nv_bfloat16 g_xt_l[(size_t)BB * UU * SS];
__device__ __nv_bfloat16 g_qkvh[(size_t)BB * 3 * UU * SS];
__device__ __nv_bfloat16 g_qkvl[(size_t)BB * 3 * UU * SS];
__device__ __nv_bfloat16 g_ct_h[(size_t)BB * UU * SS];
__device__ __nv_bfloat16 g_ct_l[(size_t)BB * UU * SS];

// ---------------------------------------------------------------------------
// cp.async helpers
// ---------------------------------------------------------------------------
__device__ __forceinline__ uint32_t smaddr(const void* p) {
    return (uint32_t)__cvta_generic_to_shared(p);
}
#define CP16(sm, gp) asm volatile("cp.async.cg.shared.global [%0], [%1], 16;" \
                                  :: "r"(sm), "l"(gp))
#define CP_COMMIT()  asm volatile("cp.async.commit_group;")
#define CP_WAIT2()   asm volatile("cp.async.wait_group 2;")
#define CP_WAIT1()   asm volatile("cp.async.wait_group 1;")
#define CP_WAIT0()   asm volatile("cp.async.wait_group 0;")

// ---------------------------------------------------------------------------
// Mask detect / normalize + coef (proven)
// ---------------------------------------------------------------------------
__global__ void detect_mask_kernel(const unsigned char* __restrict__ raw) {
    __shared__ int nz[4];
    if (threadIdx.x < 4) nz[threadIdx.x] = 0;
    __syncthreads();
    int c0 = 0, c1 = 0;
    for (int i = threadIdx.x * 4; i < (1 << 20); i += blockDim.x * 4) {
        uchar4 v = *(const uchar4*)(raw + i);
        c0 += (v.x != 0);
        c1 += (v.y != 0);
    }
    atomicAdd(&nz[0], c0);
    atomicAdd(&nz[1], c1);
    __syncthreads();
    if (threadIdx.x == 0)
        g_mode = (nz[1] > 0) ? 0 : (nz[0] > 0 ? 1 : 2);
}
__global__ void normalize_mask_kernel(const void* __restrict__ raw,
                                      unsigned char* __restrict__ dst) {
    size_t i = ((size_t)blockIdx.x * blockDim.x + threadIdx.x) * 4;
    if (i >= NMASK) return;
    int mode = g_mode;
    uchar4 o;
    if (mode == 0) {
        uchar4 v = *(const uchar4*)((const unsigned char*)raw + i);
        o = make_uchar4(v.x != 0, v.y != 0, v.z != 0, v.w != 0);
    } else if (mode == 1) {
        int4 v = *(const int4*)((const int*)raw + i);
        o = make_uchar4(v.x != 0, v.y != 0, v.z != 0, v.w != 0);
    } else {
        float4 v = *(const float4*)((const float*)raw + i);
        o = make_uchar4(v.x != 0.f, v.y != 0.f, v.z != 0.f, v.w != 0.f);
    }
    *(uchar4*)(dst + i) = o;
}
__global__ void coef_kernel(const unsigned char* __restrict__ mask,
                            float* __restrict__ coef) {
    int row = blockIdx.x;
    int tid = threadIdx.x;
    const uchar4 v = ((const uchar4*)(mask + (size_t)row * SS))[tid];
    int s = (int)v.x + (int)v.y + (int)v.z + (int)v.w;
#pragma unroll
    for (int o = 16; o; o >>= 1) s += __shfl_xor_sync(0xffffffffu, s, o);
    __shared__ int red[8];
    if ((tid & 31) == 0) red[tid >> 5] = s;
    __syncthreads();
    if (tid < 8) {
        int t = red[tid];
#pragma unroll
        for (int o = 4; o; o >>= 1) t += __shfl_xor_sync(0xffu, t, o);
        if (tid == 0) coef[row] = SCALE / (float)(t > 0 ? t : 1);
    }
}

// ---------------------------------------------------------------------------
// split fp32 -> hi/lo bf16 planes
// ---------------------------------------------------------------------------
__global__ void conv_split_planar(const float* __restrict__ src,
                                  __nv_bfloat16* __restrict__ dh,
                                  __nv_bfloat16* __restrict__ dl, int n) {
    int i0 = (blockIdx.x * blockDim.x + threadIdx.x) * 8;
    if (i0 >= n) return;
    ushort hs[8], ls[8];
#pragma unroll
    for (int j = 0; j < 8; j++) {
        float v = src[i0 + j];
        __nv_bfloat16 h = __float2bfloat16_rn(v);
        __nv_bfloat16 l = __float2bfloat16_rn(v - __bfloat162float(h));
        hs[j] = __bfloat16_as_ushort(h);
        ls[j] = __bfloat16_as_ushort(l);
    }
    *(uint4*)(dh + i0) = make_uint4((uint32_t)hs[0] | ((uint32_t)hs[1] << 16),
                                    (uint32_t)hs[2] | ((uint32_t)hs[3] << 16),
                                    (uint32_t)hs[4] | ((uint32_t)hs[5] << 16),
                                    (uint32_t)hs[6] | ((uint32_t)hs[7] << 16));
    *(uint4*)(dl + i0) = make_uint4((uint32_t)ls[0] | ((uint32_t)ls[1] << 16),
                                    (uint32_t)ls[2] | ((uint32_t)ls[3] << 16),
                                    (uint32_t)ls[4] | ((uint32_t)ls[5] << 16),
                                    (uint32_t)ls[6] | ((uint32_t)ls[7] << 16));
}

// ---------------------------------------------------------------------------
// transpose+split: [b][k][n] fp32 -> [b][n][k] bf16 planes
// ---------------------------------------------------------------------------
__global__ void conv_transpose_planar(const float* __restrict__ src,
                                      __nv_bfloat16* __restrict__ dh,
                                      __nv_bfloat16* __restrict__ dl) {
    __shared__ float t[32][33];
    const int b = blockIdx.z;
    const int k0 = blockIdx.y * 32, n0 = blockIdx.x * 32;
    const float* s = src + ((size_t)b << 20);
    const int tx = threadIdx.x, ty = threadIdx.y;
#pragma unroll
    for (int j = 0; j < 32; j += 8)
        t[ty + j][tx] = s[(size_t)(k0 + ty + j) * 1024 + n0 + tx];
    __syncthreads();
    const int tid = ty * 32 + tx;
    const int nl = tid >> 3;
    const int kg = (tid & 7) * 4;
    ushort hs[4], ls[4];
#pragma unroll
    for (int i = 0; i < 4; i++) {
        float v = t[kg + i][nl];
        __nv_bfloat16 h = __float2bfloat16_rn(v);
        __nv_bfloat16 l = __float2bfloat16_rn(v - __bfloat162float(h));
        hs[i] = __bfloat16_as_ushort(h);
        ls[i] = __bfloat16_as_ushort(l);
    }
    size_t o = ((size_t)b << 20) + (size_t)(n0 + nl) * 1024 + k0 + kg;
    *(uint2*)(dh + o) = make_uint2((uint32_t)hs[0] | ((uint32_t)hs[1] << 16),
                                   (uint32_t)hs[2] | ((uint32_t)hs[3] << 16));
    *(uint2*)(dl + o) = make_uint2((uint32_t)ls[0] | ((uint32_t)ls[1] << 16),
                                   (uint32_t)ls[2] | ((uint32_t)ls[3] << 16));
}

// ---------------------------------------------------------------------------
// WMMA split-bf16 3-term GEMM. CTA 128x256, warp 64x64, 3-stage cp.async.
// ---------------------------------------------------------------------------
#define GM 128
#define GN 256
#define GBK 32
#define GPAD 40
#define ASTG (GM * GPAD)
#define BSTG (GN * GPAD)
#define GSTAGE (ASTG + BSTG)
#define GEMM_SMEM (3 * GSTAGE * 2)
#define GCHUNKS 96

__global__ void __launch_bounds__(256)
gemm_wmma(const __nv_bfloat16* __restrict__ Ah, const __nv_bfloat16* __restrict__ Al,
          const __nv_bfloat16* __restrict__ Bh, const __nv_bfloat16* __restrict__ Bl,
          float* __restrict__ C, size_t cStride) {
    extern __shared__ __align__(16) __nv_bfloat16 gsm[];

    const int tid = threadIdx.x;
    const int wid = tid >> 5;
    const int wm = wid >> 2;          // 0..1
    const int wn = wid & 3;           // 0..3
    const int m0 = blockIdx.y * GM;
    const int n0 = blockIdx.x * GN;
    const size_t bOff = (size_t)blockIdx.z << 20;
    float* Cp = C + (size_t)blockIdx.z * cStride;

    wmma::fragment<wmma::accumulator, 16, 16, 16, float> acc[4][4];
#pragma unroll
    for (int i = 0; i < 4; i++)
#pragma unroll
        for (int j = 0; j < 4; j++) wmma::fill_fragment(acc[i][j], 0.0f);

    auto stage = [&](int c, int s) {
        const int phase = c >> 5;
        const int kk = (c & 31) * GBK;
        const __nv_bfloat16* Ap = (phase == 1) ? Al : Ah;
        const __nv_bfloat16* Bp = ((phase == 2) ? Bl : Bh) + bOff;
        __nv_bfloat16* As = gsm + s * GSTAGE;
        __nv_bfloat16* Bs = As + ASTG;
#pragma unroll
        for (int i = 0; i < 2; i++) {
            int idx = tid + i * 256;          // 0..511
            int r = idx >> 2, sg = (idx & 3) * 8;
            CP16(smaddr(As + r * GPAD + sg), Ap + (size_t)(m0 + r) * 1024 + kk + sg);
        }
#pragma unroll
        for (int i = 0; i < 4; i++) {
            int idx = tid + i * 256;          // 0..1023
            int r = idx >> 2, sg = (idx & 3) * 8;
            CP16(smaddr(Bs + r * GPAD + sg), Bp + (size_t)(n0 + r) * 1024 + kk + sg);
        }
    };

    stage(0, 0); CP_COMMIT();
    stage(1, 1); CP_COMMIT();

    for (int c = 0; c < GCHUNKS; ++c) {
        if (c + 2 < GCHUNKS) {
            stage(c + 2, (c + 2) % 3);
            CP_COMMIT();
            CP_WAIT2();
        } else if (c + 1 < GCHUNKS) {
            CP_WAIT1();
        } else {
            CP_WAIT0();
        }
        __syncthreads();
        const __nv_bfloat16* As = gsm + (c % 3) * GSTAGE;
        const __nv_bfloat16* Bs = As + ASTG;
#pragma unroll
        for (int ks = 0; ks < 2; ks++) {
            wmma::fragment<wmma::matrix_a, 16, 16, 16, __nv_bfloat16, wmma::row_major> fa[4];
            wmma::fragment<wmma::matrix_b, 16, 16, 16, __nv_bfloat16, wmma::col_major> fb[4];
#pragma unroll
            for (int i = 0; i < 4; i++)
                wmma::load_matrix_sync(fa[i], As + (wm * 64 + i * 16) * GPAD + ks * 16, GPAD);
#pragma unroll
            for (int j = 0; j < 4; j++)
                wmma::load_matrix_sync(fb[j], Bs + (wn * 64 + j * 16) * GPAD + ks * 16, GPAD);
#pragma unroll
            for (int i = 0; i < 4; i++)
#pragma unroll
                for (int j = 0; j < 4; j++)
                    wmma::mma_sync(acc[i][j], fa[i], fb[j], acc[i][j]);
        }
        __syncthreads();
    }

#pragma unroll
    for (int i = 0; i < 4; i++)
#pragma unroll
        for (int j = 0; j < 4; j++)
            wmma::store_matrix_sync(
                Cp + (size_t)(m0 + wm * 64 + i * 16) * 1024 + n0 + wn * 64 + j * 16,
                acc[i][j], 1024, wmma::mem_row_major);
}

// ---------------------------------------------------------------------------
// WMMA attention with resident Q planes.
// ---------------------------------------------------------------------------
#define QP   136
#define FPAD 132
#define OFF_QH 0
#define OFF_QL 34816
#define OFF_AH 69632
#define OFF_AL 104448
#define OFF_V  139264                 // Vh | Vl ; Asm fp32 aliases here
#define OFF_KS 208896
#define OFF_CF 217600
#define ATTN_SMEM 218112

__global__ void __launch_bounds__(256)
attn_wmma(const __nv_bfloat16* __restrict__ qh, const __nv_bfloat16* __restrict__ ql,
          const unsigned char* __restrict__ mask, const float* __restrict__ coef,
          __nv_bfloat16* __restrict__ cth, __nv_bfloat16* __restrict__ ctl) {
    extern __shared__ char sm[];
    __nv_bfloat16* QhS = (__nv_bfloat16*)(sm + OFF_QH);
    __nv_bfloat16* QlS = (__nv_bfloat16*)(sm + OFF_QL);
    __nv_bfloat16* AhS = (__nv_bfloat16*)(sm + OFF_AH);
    __nv_bfloat16* AlS = (__nv_bfloat16*)(sm + OFF_AL);
    float*         Asm = (float*)(sm + OFF_V);
    __nv_bfloat16* VhS = (__nv_bfloat16*)(sm + OFF_V);
    __nv_bfloat16* VlS = (__nv_bfloat16*)(sm + OFF_V + 34816);
    __nv_bfloat16* Ks  = (__nv_bfloat16*)(sm + OFF_KS);
    float*         cfs = (float*)(sm + OFF_CF);

    const int q0 = blockIdx.x * 128;
    const int h  = blockIdx.y;
    const int b  = blockIdx.z;
    const int tid = threadIdx.x;
    const int wid = tid >> 5;
    const int wm = wid >> 2;          // 0..1
    const int wn = wid & 3;           // 0..3

    const size_t base = ((size_t)b * 3 * UU + (size_t)h * CC) * SS;
    const __nv_bfloat16* Qh = qh + base;
    const __nv_bfloat16* Ql = ql + base;
    const __nv_bfloat16* Kh = Qh + (size_t)UU * SS;
    const __nv_bfloat16* Kl = Ql + (size_t)UU * SS;
    const __nv_bfloat16* Vh = Qh + (size_t)2 * UU * SS;
    const __nv_bfloat16* Vl = Ql + (size_t)2 * UU * SS;
    const unsigned char* mg = mask + ((size_t)(b * SS + q0)) * SS;

    if (tid < 128) cfs[tid] = coef[b * SS + q0 + tid];
    // resident Q: both planes, [c][q] with pad QP
#pragma unroll
    for (int it = 0; it < 16; it++) {
        int idx = tid + it * 256;           // 0..4095
        int pl = idx >> 11;
        int i2 = idx & 2047;
        int r = i2 >> 4, sg = (i2 & 15) * 8;
        const __nv_bfloat16* src = pl ? Ql : Qh;
        __nv_bfloat16* dst = pl ? QlS : QhS;
        *(uint4*)&dst[r * QP + sg] = *(const uint4*)(src + (size_t)r * SS + q0 + sg);
    }
    __syncthreads();

    wmma::fragment<wmma::accumulator, 16, 16, 16, float> accC[4][2];
#pragma unroll
    for (int i = 0; i < 4; i++)
#pragma unroll
        for (int j = 0; j < 2; j++) wmma::fill_fragment(accC[i][j], 0.0f);

    for (int kt = 0; kt < 8; kt++) {
        const int k0 = kt * 128;

        // ---- QK^T (3-term; Kh shared by Qh and Ql phases) ----
        wmma::fragment<wmma::accumulator, 16, 16, 16, float> accA[4][2];
#pragma unroll
        for (int i = 0; i < 4; i++)
#pragma unroll
            for (int j = 0; j < 2; j++) wmma::fill_fragment(accA[i][j], 0.0f);

        for (int kpl = 0; kpl < 2; kpl++) {
            const __nv_bfloat16* Kp = kpl ? Kl : Kh;
            for (int cc = 0; cc < 4; cc++) {
                __syncthreads();
#pragma unroll
                for (int i = 0; i < 2; i++) {
                    int idx = tid + i * 256;   // 0..511
                    int r = idx >> 4, sg = (idx & 15) * 8;
                    *(uint4*)&Ks[r * QP + sg] =
                        *(const uint4*)(Kp + (size_t)(cc * 32 + r) * SS + k0 + sg);
                }
                __syncthreads();
#pragma unroll
                for (int ks = 0; ks < 2; ks++) {
                    wmma::fragment<wmma::matrix_b, 16, 16, 16, __nv_bfloat16, wmma::row_major> fb[2];
#pragma unroll
                    for (int j = 0; j < 2; j++)
                        wmma::load_matrix_sync(fb[j], &Ks[ks * 16 * QP + wn * 32 + j * 16], QP);
                    wmma::fragment<wmma::matrix_a, 16, 16, 16, __nv_bfloat16, wmma::col_major> fa[4];
#pragma unroll
                    for (int i = 0; i < 4; i++)
                        wmma::load_matrix_sync(fa[i],
                            &QhS[(cc * 32 + ks * 16) * QP + wm * 64 + i * 16], QP);
#pragma unroll
                    for (int i = 0; i < 4; i++)
#pragma unroll
                        for (int j = 0; j < 2; j++)
                            wmma::mma_sync(accA[i][j], fa[i], fb[j], accA[i][j]);
                    if (kpl == 0) {
#pragma unroll
                        for (int i = 0; i < 4; i++)
                            wmma::load_matrix_sync(fa[i],
                                &QlS[(cc * 32 + ks * 16) * QP + wm * 64 + i * 16], QP);
#pragma unroll
                        for (int i = 0; i < 4; i++)
#pragma unroll
                            for (int j = 0; j < 2; j++)
                                wmma::mma_sync(accA[i][j], fa[i], fb[j], accA[i][j]);
                    }
                }
            }
        }

        // ---- scores -> smem fp32 (aliases V region; previous AV done) ----
#pragma unroll
        for (int i = 0; i < 4; i++)
#pragma unroll
            for (int j = 0; j < 2; j++)
                wmma::store_matrix_sync(
                    &Asm[(size_t)(wm * 64 + i * 16) * FPAD + wn * 32 + j * 16],
                    accA[i][j], FPAD, wmma::mem_row_major);
        __syncthreads();

        // ---- normalize + split ----
        {
            const int q = tid >> 1;
            const int hf = tid & 1;
            const float cf = cfs[q];
            const unsigned char* mrow = mg + (size_t)q * SS + k0 + hf * 64;
            uint4 mv[4];
#pragma unroll
            for (int i = 0; i < 4; i++) mv[i] = *(const uint4*)(mrow + i * 16);
            unsigned char mb[64];
            *(uint4*)(mb +  0) = mv[0];
            *(uint4*)(mb + 16) = mv[1];
            *(uint4*)(mb + 32) = mv[2];
            *(uint4*)(mb + 48) = mv[3];
            const int cbase = hf * 64;
#pragma unroll 16
            for (int j = 0; j < 64; j++) {
                float v = Asm[(size_t)q * FPAD + cbase + j];
                v = mb[j] ? fmaxf(v, 0.f) * cf : 0.f;
                __nv_bfloat16 hh = __float2bfloat16_rn(v);
                __nv_bfloat16 ll = __float2bfloat16_rn(v - __bfloat162float(hh));
                AhS[q * QP + cbase + j] = hh;
                AlS[q * QP + cbase + j] = ll;
            }
        }
        __syncthreads();

        // ---- stage V tiles ----
#pragma unroll
        for (int it = 0; it < 16; it++) {
            int idx = tid + (it & 7) * 256;   // 0..2047
            int r = idx >> 4, sg = (idx & 15) * 8;
            __nv_bfloat16* dst = (it < 8) ? VhS : VlS;
            const __nv_bfloat16* src = (it < 8) ? Vh : Vl;
            *(uint4*)&dst[r * QP + sg] = *(const uint4*)(src + (size_t)r * SS + k0 + sg);
        }
        __syncthreads();

        // ---- A' V^T (3-term) ----
        for (int ph = 0; ph < 3; ph++) {
            const __nv_bfloat16* Ap = (ph == 1) ? AlS : AhS;
            const __nv_bfloat16* Vp = (ph == 2) ? VlS : VhS;
#pragma unroll
            for (int kc = 0; kc < 8; kc++) {
                wmma::fragment<wmma::matrix_a, 16, 16, 16, __nv_bfloat16, wmma::row_major> fa[4];
                wmma::fragment<wmma::matrix_b, 16, 16, 16, __nv_bfloat16, wmma::col_major> fb[2];
#pragma unroll
                for (int i = 0; i < 4; i++)
                    wmma::load_matrix_sync(fa[i], &Ap[(wm * 64 + i * 16) * QP + kc * 16], QP);
#pragma unroll
                for (int j = 0; j < 2; j++)
                    wmma::load_matrix_sync(fb[j], &Vp[(wn * 32 + j * 16) * QP + kc * 16], QP);
#pragma unroll
                for (int i = 0; i < 4; i++)
#pragma unroll
                    for (int j = 0; j < 2; j++)
                        wmma::mma_sync(accC[i][j], fa[i], fb[j], accC[i][j]);
            }
        }
        __syncthreads();
    }

    // ---- epilogue: split planes ct[b][q0+q][h*128+c] ----
#pragma unroll
    for (int i = 0; i < 4; i++)
#pragma unroll
        for (int j = 0; j < 2; j++)
            wmma::store_matrix_sync(
                &Asm[(size_t)(wm * 64 + i * 16) * FPAD + wn * 32 + j * 16],
                accC[i][j], FPAD, wmma::mem_row_major);
    __syncthreads();
    {
        const int q = tid >> 1;
        const int hf = tid & 1;
        ushort hs[8], ls[8];
        size_t o = ((size_t)b << 20) + (size_t)(q0 + q) * 1024 + h * CC + hf * 64;
#pragma unroll
        for (int g = 0; g < 8; g++) {
#pragma unroll
            for (int j = 0; j < 8; j++) {
                float v = Asm[(size_t)q * FPAD + hf * 64 + g * 8 + j];
                __nv_bfloat16 hh = __float2bfloat16_rn(v);
                __nv_bfloat16 ll = __float2bfloat16_rn(v - __bfloat162float(hh));
                hs[j] = __bfloat16_as_ushort(hh);
                ls[j] = __bfloat16_as_ushort(ll);
            }
            *(uint4*)(cth + o + g * 8) =
                make_uint4((uint32_t)hs[0] | ((uint32_t)hs[1] << 16),
                           (uint32_t)hs[2] | ((uint32_t)hs[3] << 16),
                           (uint32_t)hs[4] | ((uint32_t)hs[5] << 16),
                           (uint32_t)hs[6] | ((uint32_t)hs[7] << 16));
            *(uint4*)(ctl + o + g * 8) =
                make_uint4((uint32_t)ls[0] | ((uint32_t)ls[1] << 16),
                           (uint32_t)ls[2] | ((uint32_t)ls[3] << 16),
                           (uint32_t)ls[4] | ((uint32_t)ls[5] << 16),
                           (uint32_t)ls[6] | ((uint32_t)ls[7] << 16));
        }
    }
}

// ---------------------------------------------------------------------------
// Launch
// ---------------------------------------------------------------------------
extern "C" void kernel_launch(void* const* d_in, const int* in_sizes, int n_in,
                              void* d_out, int out_size) {
    const float* x     = (const float*)d_in[0];
    const void*  maskr = d_in[1];
    const float* w_qkv = (const float*)d_in[2];
    const float* w_out = (const float*)d_in[3];
    float*       out   = (float*)d_out;

    void *p_qkv, *p_coef, *p_mask;
    void *p_wqh, *p_wql, *p_woh, *p_wol, *p_xth, *p_xtl;
    void *p_qvh, *p_qvl, *p_cth, *p_ctl;
    cudaGetSymbolAddress(&p_qkv,  g_qkv);
    cudaGetSymbolAddress(&p_coef, g_coef);
    cudaGetSymbolAddress(&p_mask, g_mask);
    cudaGetSymbolAddress(&p_wqh,  g_wq_h);
    cudaGetSymbolAddress(&p_wql,  g_wq_l);
    cudaGetSymbolAddress(&p_woh,  g_wo_h);
    cudaGetSymbolAddress(&p_wol,  g_wo_l);
    cudaGetSymbolAddress(&p_xth,  g_xt_h);
    cudaGetSymbolAddress(&p_xtl,  g_xt_l);
    cudaGetSymbolAddress(&p_qvh,  g_qkvh);
    cudaGetSymbolAddress(&p_qvl,  g_qkvl);
    cudaGetSymbolAddress(&p_cth,  g_ct_h);
    cudaGetSymbolAddress(&p_ctl,  g_ct_l);
    float* qkv  = (float*)p_qkv;
    float* coef = (float*)p_coef;
    unsigned char* mask = (unsigned char*)p_mask;
    __nv_bfloat16* wqh = (__nv_bfloat16*)p_wqh;
    __nv_bfloat16* wql = (__nv_bfloat16*)p_wql;
    __nv_bfloat16* woh = (__nv_bfloat16*)p_woh;
    __nv_bfloat16* wol = (__nv_bfloat16*)p_wol;
    __nv_bfloat16* xth = (__nv_bfloat16*)p_xth;
    __nv_bfloat16* xtl = (__nv_bfloat16*)p_xtl;
    __nv_bfloat16* qvh = (__nv_bfloat16*)p_qvh;
    __nv_bfloat16* qvl = (__nv_bfloat16*)p_qvl;
    __nv_bfloat16* cth = (__nv_bfloat16*)p_cth;
    __nv_bfloat16* ctl = (__nv_bfloat16*)p_ctl;

    cudaFuncSetAttribute(gemm_wmma, cudaFuncAttributeMaxDynamicSharedMemorySize,
                         GEMM_SMEM);
    cudaFuncSetAttribute(attn_wmma, cudaFuncAttributeMaxDynamicSharedMemorySize,
                         ATTN_SMEM);

    // mask + coef
    detect_mask_kernel<<<1, 256>>>((const unsigned char*)maskr);
    normalize_mask_kernel<<<(int)(NMASK / 4 / 256), 256>>>(maskr, mask);
    coef_kernel<<<BB * SS, 256>>>(mask, coef);

    // operand prep
    conv_split_planar<<<3 * UU * UU / 8 / 256, 256>>>(w_qkv, wqh, wql, 3 * UU * UU);
    conv_split_planar<<<UU * UU / 8 / 256, 256>>>(w_out, woh, wol, UU * UU);
    conv_transpose_planar<<<dim3(32, 32, BB), dim3(32, 8)>>>(x, xth, xtl);

    // QKV projection
    gemm_wmma<<<dim3(SS / GN, 3 * UU / GM, BB), 256, GEMM_SMEM>>>(
        wqh, wql, xth, xtl, qkv, (size_t)3 * UU * SS);

    // split qkv -> bf16 planes
    conv_split_planar<<<(int)((size_t)BB * 3 * UU * SS / 8 / 256), 256>>>(
        qkv, qvh, qvl, (int)((size_t)BB * 3 * UU * SS));

    // WMMA attention -> ctx^T planes
    attn_wmma<<<dim3(SS / 128, HH, BB), 256, ATTN_SMEM>>>(
        qvh, qvl, mask, coef, cth, ctl);

    // output projection
    gemm_wmma<<<dim3(SS / GN, UU / GM, BB), 256, GEMM_SMEM>>>(
        woh, wol, cth, ctl, out, (size_t)UU * SS);
}

// round 12
// speedup vs baseline: 1.0435x; 1.0435x over previous
#include <cuda_runtime.h>
#include <cuda_bf16.h>
#include <mma.h>
#include <cstdint>

using namespace nvcuda;

#define BB   16
#define UU   1024
#define HH   8
#define CC   128
#define SS   1024
#define SCALE 0.08838834764831843f   // 1/sqrt(128)

#define NMASK ((size_t)BB * SS * SS)

// ---------------------------------------------------------------------------
// Scratch
// ---------------------------------------------------------------------------
__device__ float g_coef[BB * SS];
__device__ unsigned char g_mask[NMASK];
__device__ int g_mode;
__device__ __nv_bfloat16 g_wq_h[(size_t)3 * UU * UU];
__device__ __nv_bfloat16 g_wq_l[(size_t)3 * UU * UU];
__device__ __nv_bfloat16 g_wo_h[(size_t)UU * UU];
__device__ __nv_bfloat16 g_wo_l[(size_t)UU * UU];
__device__ __nv_bfloat16 g_xt_h[(size_t)BB * UU * SS];
__device__ __nv_bfloat16 g_xt_l[(size_t)BB * UU * SS];
__device__ __nv_bfloat16 g_qkvh[(size_t)BB * 3 * UU * SS]; // qkv hi plane
__device__ __nv_bfloat16 g_qkvl[(size_t)BB * 3 * UU * SS]; // qkv lo plane
__device__ __nv_bfloat16 g_ct_h[(size_t)BB * UU * SS];     // ctx^T planes
__device__ __nv_bfloat16 g_ct_l[(size_t)BB * UU * SS];

// ---------------------------------------------------------------------------
// cp.async helpers
// ---------------------------------------------------------------------------
__device__ __forceinline__ uint32_t smaddr(const void* p) {
    return (uint32_t)__cvta_generic_to_shared(p);
}
#define CP16(sm, gp) asm volatile("cp.async.cg.shared.global [%0], [%1], 16;" \
                                  :: "r"(sm), "l"(gp))
#define CP_COMMIT()  asm volatile("cp.async.commit_group;")
#define CP_WAIT1()   asm volatile("cp.async.wait_group 1;")
#define CP_WAIT0()   asm volatile("cp.async.wait_group 0;")

// ---------------------------------------------------------------------------
// Mask detect / normalize + coef (proven)
// ---------------------------------------------------------------------------
__global__ void detect_mask_kernel(const unsigned char* __restrict__ raw) {
    __shared__ int nz[4];
    if (threadIdx.x < 4) nz[threadIdx.x] = 0;
    __syncthreads();
    int c0 = 0, c1 = 0;
    for (int i = threadIdx.x * 4; i < (1 << 20); i += blockDim.x * 4) {
        uchar4 v = *(const uchar4*)(raw + i);
        c0 += (v.x != 0);
        c1 += (v.y != 0);
    }
    atomicAdd(&nz[0], c0);
    atomicAdd(&nz[1], c1);
    __syncthreads();
    if (threadIdx.x == 0)
        g_mode = (nz[1] > 0) ? 0 : (nz[0] > 0 ? 1 : 2);
}
__global__ void normalize_mask_kernel(const void* __restrict__ raw,
                                      unsigned char* __restrict__ dst) {
    size_t i = ((size_t)blockIdx.x * blockDim.x + threadIdx.x) * 4;
    if (i >= NMASK) return;
    int mode = g_mode;
    uchar4 o;
    if (mode == 0) {
        uchar4 v = *(const uchar4*)((const unsigned char*)raw + i);
        o = make_uchar4(v.x != 0, v.y != 0, v.z != 0, v.w != 0);
    } else if (mode == 1) {
        int4 v = *(const int4*)((const int*)raw + i);
        o = make_uchar4(v.x != 0, v.y != 0, v.z != 0, v.w != 0);
    } else {
        float4 v = *(const float4*)((const float*)raw + i);
        o = make_uchar4(v.x != 0.f, v.y != 0.f, v.z != 0.f, v.w != 0.f);
    }
    *(uchar4*)(dst + i) = o;
}
__global__ void coef_kernel(const unsigned char* __restrict__ mask,
                            float* __restrict__ coef) {
    int row = blockIdx.x;
    int tid = threadIdx.x;
    const uchar4 v = ((const uchar4*)(mask + (size_t)row * SS))[tid];
    int s = (int)v.x + (int)v.y + (int)v.z + (int)v.w;
#pragma unroll
    for (int o = 16; o; o >>= 1) s += __shfl_xor_sync(0xffffffffu, s, o);
    __shared__ int red[8];
    if ((tid & 31) == 0) red[tid >> 5] = s;
    __syncthreads();
    if (tid < 8) {
        int t = red[tid];
#pragma unroll
        for (int o = 4; o; o >>= 1) t += __shfl_xor_sync(0xffu, t, o);
        if (tid == 0) coef[row] = SCALE / (float)(t > 0 ? t : 1);
    }
}

// ---------------------------------------------------------------------------
// split fp32 -> hi/lo bf16 planes (weights)
// ---------------------------------------------------------------------------
__global__ void conv_split_planar(const float* __restrict__ src,
                                  __nv_bfloat16* __restrict__ dh,
                                  __nv_bfloat16* __restrict__ dl, int n) {
    int i0 = (blockIdx.x * blockDim.x + threadIdx.x) * 8;
    if (i0 >= n) return;
    ushort hs[8], ls[8];
#pragma unroll
    for (int j = 0; j < 8; j++) {
        float v = src[i0 + j];
        __nv_bfloat16 h = __float2bfloat16_rn(v);
        __nv_bfloat16 l = __float2bfloat16_rn(v - __bfloat162float(h));
        hs[j] = __bfloat16_as_ushort(h);
        ls[j] = __bfloat16_as_ushort(l);
    }
    *(uint4*)(dh + i0) = make_uint4((uint32_t)hs[0] | ((uint32_t)hs[1] << 16),
                                    (uint32_t)hs[2] | ((uint32_t)hs[3] << 16),
                                    (uint32_t)hs[4] | ((uint32_t)hs[5] << 16),
                                    (uint32_t)hs[6] | ((uint32_t)hs[7] << 16));
    *(uint4*)(dl + i0) = make_uint4((uint32_t)ls[0] | ((uint32_t)ls[1] << 16),
                                    (uint32_t)ls[2] | ((uint32_t)ls[3] << 16),
                                    (uint32_t)ls[4] | ((uint32_t)ls[5] << 16),
                                    (uint32_t)ls[6] | ((uint32_t)ls[7] << 16));
}

// ---------------------------------------------------------------------------
// transpose+split: [b][k][n] fp32 -> [b][n][k] bf16 planes (x)
// ---------------------------------------------------------------------------
__global__ void conv_transpose_planar(const float* __restrict__ src,
                                      __nv_bfloat16* __restrict__ dh,
                                      __nv_bfloat16* __restrict__ dl) {
    __shared__ float t[32][33];
    const int b = blockIdx.z;
    const int k0 = blockIdx.y * 32, n0 = blockIdx.x * 32;
    const float* s = src + ((size_t)b << 20);
    const int tx = threadIdx.x, ty = threadIdx.y;
#pragma unroll
    for (int j = 0; j < 32; j += 8)
        t[ty + j][tx] = s[(size_t)(k0 + ty + j) * 1024 + n0 + tx];
    __syncthreads();
    const int tid = ty * 32 + tx;
    const int nl = tid >> 3;
    const int kg = (tid & 7) * 4;
    ushort hs[4], ls[4];
#pragma unroll
    for (int i = 0; i < 4; i++) {
        float v = t[kg + i][nl];
        __nv_bfloat16 h = __float2bfloat16_rn(v);
        __nv_bfloat16 l = __float2bfloat16_rn(v - __bfloat162float(h));
        hs[i] = __bfloat16_as_ushort(h);
        ls[i] = __bfloat16_as_ushort(l);
    }
    size_t o = ((size_t)b << 20) + (size_t)(n0 + nl) * 1024 + k0 + kg;
    *(uint2*)(dh + o) = make_uint2((uint32_t)hs[0] | ((uint32_t)hs[1] << 16),
                                   (uint32_t)hs[2] | ((uint32_t)hs[3] << 16));
    *(uint2*)(dl + o) = make_uint2((uint32_t)ls[0] | ((uint32_t)ls[1] << 16),
                                   (uint32_t)ls[2] | ((uint32_t)ls[3] << 16));
}

// ---------------------------------------------------------------------------
// WMMA split-bf16 3-term GEMM (R9-proven structure: 128x128 CTA, warp 64x32,
// 2-stage cp.async). Epilogue: either fp32 C, or fused split to Dh/Dl planes.
// ---------------------------------------------------------------------------
#define GBK 32
#define GPAD 40
#define GCHUNKS 96
#define EPAD 132

__global__ void __launch_bounds__(256, 2)
gemm_wmma(const __nv_bfloat16* __restrict__ Ah, const __nv_bfloat16* __restrict__ Al,
          const __nv_bfloat16* __restrict__ Bh, const __nv_bfloat16* __restrict__ Bl,
          float* __restrict__ C,
          __nv_bfloat16* __restrict__ Dh, __nv_bfloat16* __restrict__ Dl,
          size_t cStride) {
    // one static buffer, reused: staging (2 stages x (A+B)) then fp32 epilogue
    __shared__ __align__(16) __nv_bfloat16 sbuf[2 * 2 * 128 * GPAD]; // 40960 B

    const int tid = threadIdx.x;
    const int wid = tid >> 5;
    const int wm = wid >> 2;          // 0..1
    const int wn = wid & 3;           // 0..3
    const int m0 = blockIdx.y * 128;
    const int n0 = blockIdx.x * 128;
    const size_t bOff = (size_t)blockIdx.z << 20;

    wmma::fragment<wmma::accumulator, 16, 16, 16, float> acc[4][2];
#pragma unroll
    for (int i = 0; i < 4; i++)
#pragma unroll
        for (int j = 0; j < 2; j++) wmma::fill_fragment(acc[i][j], 0.0f);

    auto stage = [&](int c, int buf) {
        const int phase = c >> 5;
        const int kk = (c & 31) * GBK;
        const __nv_bfloat16* Ap = (phase == 1) ? Al : Ah;
        const __nv_bfloat16* Bp = ((phase == 2) ? Bl : Bh) + bOff;
        __nv_bfloat16* As = sbuf + buf * (2 * 128 * GPAD);
        __nv_bfloat16* Bs = As + 128 * GPAD;
#pragma unroll
        for (int i = 0; i < 2; i++) {
            int idx = tid + i * 256;
            int r = idx >> 2, sg = (idx & 3) * 8;
            CP16(smaddr(As + r * GPAD + sg), Ap + (size_t)(m0 + r) * 1024 + kk + sg);
            CP16(smaddr(Bs + r * GPAD + sg), Bp + (size_t)(n0 + r) * 1024 + kk + sg);
        }
    };

    stage(0, 0);
    CP_COMMIT();

    for (int c = 0; c < GCHUNKS; ++c) {
        if (c + 1 < GCHUNKS) {
            stage(c + 1, (c + 1) & 1);
            CP_COMMIT();
            CP_WAIT1();
        } else {
            CP_WAIT0();
        }
        __syncthreads();
        const __nv_bfloat16* As = sbuf + (c & 1) * (2 * 128 * GPAD);
        const __nv_bfloat16* Bs = As + 128 * GPAD;
#pragma unroll
        for (int ks = 0; ks < 2; ks++) {
            wmma::fragment<wmma::matrix_a, 16, 16, 16, __nv_bfloat16, wmma::row_major> fa[4];
            wmma::fragment<wmma::matrix_b, 16, 16, 16, __nv_bfloat16, wmma::col_major> fb[2];
#pragma unroll
            for (int i = 0; i < 4; i++)
                wmma::load_matrix_sync(fa[i], As + (wm * 64 + i * 16) * GPAD + ks * 16, GPAD);
#pragma unroll
            for (int j = 0; j < 2; j++)
                wmma::load_matrix_sync(fb[j], Bs + (wn * 32 + j * 16) * GPAD + ks * 16, GPAD);
#pragma unroll
            for (int i = 0; i < 4; i++)
#pragma unroll
                for (int j = 0; j < 2; j++)
                    wmma::mma_sync(acc[i][j], fa[i], fb[j], acc[i][j]);
        }
        __syncthreads();
    }

    if (Dh == nullptr) {
        // fp32 epilogue (output projection -> d_out)
        float* Cp = C + (size_t)blockIdx.z * cStride;
#pragma unroll
        for (int i = 0; i < 4; i++)
#pragma unroll
            for (int j = 0; j < 2; j++)
                wmma::store_matrix_sync(
                    Cp + (size_t)(m0 + wm * 64 + i * 16) * 1024 + n0 + wn * 32 + j * 16,
                    acc[i][j], 1024, wmma::mem_row_major);
    } else {
        // fused split epilogue -> hi/lo planes, via smem fp32, two 64-row halves
        float* esm = (float*)sbuf;    // 64*EPAD*4 = 33792 B <= 40960 B
        __nv_bfloat16* dhp = Dh + (size_t)blockIdx.z * cStride;
        __nv_bfloat16* dlp = Dl + (size_t)blockIdx.z * cStride;
#pragma unroll
        for (int half = 0; half < 2; half++) {
            __syncthreads();
            if (wm == half) {
#pragma unroll
                for (int i = 0; i < 4; i++)
#pragma unroll
                    for (int j = 0; j < 2; j++)
                        wmma::store_matrix_sync(
                            &esm[(size_t)(i * 16) * EPAD + wn * 32 + j * 16],
                            acc[i][j], EPAD, wmma::mem_row_major);
            }
            __syncthreads();
            const int r = tid >> 2;            // 0..63
            const int cs = (tid & 3) * 32;     // 0..96
            size_t o = (size_t)(m0 + half * 64 + r) * 1024 + n0 + cs;
#pragma unroll
            for (int g = 0; g < 4; g++) {
                ushort hs[8], ls[8];
#pragma unroll
                for (int j = 0; j < 8; j++) {
                    float v = esm[(size_t)r * EPAD + cs + g * 8 + j];
                    __nv_bfloat16 hh = __float2bfloat16_rn(v);
                    __nv_bfloat16 ll = __float2bfloat16_rn(v - __bfloat162float(hh));
                    hs[j] = __bfloat16_as_ushort(hh);
                    ls[j] = __bfloat16_as_ushort(ll);
                }
                *(uint4*)(dhp + o + g * 8) =
                    make_uint4((uint32_t)hs[0] | ((uint32_t)hs[1] << 16),
                               (uint32_t)hs[2] | ((uint32_t)hs[3] << 16),
                               (uint32_t)hs[4] | ((uint32_t)hs[5] << 16),
                               (uint32_t)hs[6] | ((uint32_t)hs[7] << 16));
                *(uint4*)(dlp + o + g * 8) =
                    make_uint4((uint32_t)ls[0] | ((uint32_t)ls[1] << 16),
                               (uint32_t)ls[2] | ((uint32_t)ls[3] << 16),
                               (uint32_t)ls[4] | ((uint32_t)ls[5] << 16),
                               (uint32_t)ls[6] | ((uint32_t)ls[7] << 16));
            }
        }
    }
}

// ---------------------------------------------------------------------------
// WMMA attention (R9-proven): per (b,h,q-tile 128): QK^T 3-term, normalize,
// split, A'V^T 3-term, epilogue -> ctx^T planes.
// ---------------------------------------------------------------------------
#define APAD 136
#define FPAD 132
#define OFF_AH 0
#define OFF_AL (128 * APAD * 2)
#define OFF_B  (OFF_AL + 128 * APAD * 2)
#define OFF_QS (OFF_B + 2 * 128 * APAD * 2)
#define OFF_KS (OFF_QS + 32 * APAD * 2)
#define OFF_CF (OFF_KS + 32 * APAD * 2)
#define ATTN_SMEM (OFF_CF + 512)

__global__ void __launch_bounds__(256)
attn_wmma(const __nv_bfloat16* __restrict__ qh, const __nv_bfloat16* __restrict__ ql,
          const unsigned char* __restrict__ mask, const float* __restrict__ coef,
          __nv_bfloat16* __restrict__ cth, __nv_bfloat16* __restrict__ ctl) {
    extern __shared__ char sm[];
    __nv_bfloat16* AhS = (__nv_bfloat16*)(sm + OFF_AH);
    __nv_bfloat16* AlS = (__nv_bfloat16*)(sm + OFF_AL);
    float*         Asm = (float*)(sm + OFF_B);
    __nv_bfloat16* VhS = (__nv_bfloat16*)(sm + OFF_B);
    __nv_bfloat16* VlS = (__nv_bfloat16*)(sm + OFF_B + 128 * APAD * 2);
    __nv_bfloat16* Qs  = (__nv_bfloat16*)(sm + OFF_QS);
    __nv_bfloat16* Ks  = (__nv_bfloat16*)(sm + OFF_KS);
    float*         cfs = (float*)(sm + OFF_CF);

    const int q0 = blockIdx.x * 128;
    const int h  = blockIdx.y;
    const int b  = blockIdx.z;
    const int tid = threadIdx.x;
    const int wid = tid >> 5;
    const int wm = wid >> 2;
    const int wn = wid & 3;

    const size_t base = ((size_t)b * 3 * UU + (size_t)h * CC) * SS;
    const __nv_bfloat16* Qh = qh + base;
    const __nv_bfloat16* Ql = ql + base;
    const __nv_bfloat16* Kh = Qh + (size_t)UU * SS;
    const __nv_bfloat16* Kl = Ql + (size_t)UU * SS;
    const __nv_bfloat16* Vh = Qh + (size_t)2 * UU * SS;
    const __nv_bfloat16* Vl = Ql + (size_t)2 * UU * SS;
    const unsigned char* mg = mask + ((size_t)(b * SS + q0)) * SS;

    if (tid < 128) cfs[tid] = coef[b * SS + q0 + tid];

    wmma::fragment<wmma::accumulator, 16, 16, 16, float> accC[4][2];
#pragma unroll
    for (int i = 0; i < 4; i++)
#pragma unroll
        for (int j = 0; j < 2; j++) wmma::fill_fragment(accC[i][j], 0.0f);

    for (int kt = 0; kt < 8; kt++) {
        const int k0 = kt * 128;

        wmma::fragment<wmma::accumulator, 16, 16, 16, float> accA[4][2];
#pragma unroll
        for (int i = 0; i < 4; i++)
#pragma unroll
            for (int j = 0; j < 2; j++) wmma::fill_fragment(accA[i][j], 0.0f);

        for (int ph = 0; ph < 3; ph++) {
            const __nv_bfloat16* Qp = (ph == 1) ? Ql : Qh;
            const __nv_bfloat16* Kp = (ph == 2) ? Kl : Kh;
            for (int cc = 0; cc < 4; cc++) {
                __syncthreads();
#pragma unroll
                for (int i = 0; i < 2; i++) {
                    int idx = tid + i * 256;
                    int r = idx >> 4, sg = (idx & 15) * 8;
                    *(uint4*)&Qs[r * APAD + sg] =
                        *(const uint4*)(Qp + (size_t)(cc * 32 + r) * SS + q0 + sg);
                    *(uint4*)&Ks[r * APAD + sg] =
                        *(const uint4*)(Kp + (size_t)(cc * 32 + r) * SS + k0 + sg);
                }
                __syncthreads();
#pragma unroll
                for (int ks = 0; ks < 2; ks++) {
                    wmma::fragment<wmma::matrix_a, 16, 16, 16, __nv_bfloat16, wmma::col_major> fa[4];
                    wmma::fragment<wmma::matrix_b, 16, 16, 16, __nv_bfloat16, wmma::row_major> fb[2];
#pragma unroll
                    for (int i = 0; i < 4; i++)
                        wmma::load_matrix_sync(fa[i], &Qs[ks * 16 * APAD + wm * 64 + i * 16], APAD);
#pragma unroll
                    for (int j = 0; j < 2; j++)
                        wmma::load_matrix_sync(fb[j], &Ks[ks * 16 * APAD + wn * 32 + j * 16], APAD);
#pragma unroll
                    for (int i = 0; i < 4; i++)
#pragma unroll
                        for (int j = 0; j < 2; j++)
                            wmma::mma_sync(accA[i][j], fa[i], fb[j], accA[i][j]);
                }
            }
        }

        __syncthreads();
#pragma unroll
        for (int i = 0; i < 4; i++)
#pragma unroll
            for (int j = 0; j < 2; j++)
                wmma::store_matrix_sync(
                    &Asm[(size_t)(wm * 64 + i * 16) * FPAD + wn * 32 + j * 16],
                    accA[i][j], FPAD, wmma::mem_row_major);
        __syncthreads();

        {
            const int q = tid >> 1;
            const int hf = tid & 1;
            const float cf = cfs[q];
            const unsigned char* mrow = mg + (size_t)q * SS + k0 + hf * 64;
            uint4 mv[4];
#pragma unroll
            for (int i = 0; i < 4; i++) mv[i] = *(const uint4*)(mrow + i * 16);
            unsigned char mb[64];
            *(uint4*)(mb +  0) = mv[0];
            *(uint4*)(mb + 16) = mv[1];
            *(uint4*)(mb + 32) = mv[2];
            *(uint4*)(mb + 48) = mv[3];
            const int cbase = hf * 64;
#pragma unroll 16
            for (int j = 0; j < 64; j++) {
                float v = Asm[(size_t)q * FPAD + cbase + j];
                v = mb[j] ? fmaxf(v, 0.f) * cf : 0.f;
                __nv_bfloat16 hh = __float2bfloat16_rn(v);
                __nv_bfloat16 ll = __float2bfloat16_rn(v - __bfloat162float(hh));
                AhS[q * APAD + cbase + j] = hh;
                AlS[q * APAD + cbase + j] = ll;
            }
        }
        __syncthreads();

#pragma unroll
        for (int it = 0; it < 16; it++) {
            int idx = tid + (it & 7) * 256;
            int r = idx >> 4, sg = (idx & 15) * 8;
            __nv_bfloat16* dst = (it < 8) ? VhS : VlS;
            const __nv_bfloat16* src = (it < 8) ? Vh : Vl;
            *(uint4*)&dst[r * APAD + sg] = *(const uint4*)(src + (size_t)r * SS + k0 + sg);
        }
        __syncthreads();

        for (int ph = 0; ph < 3; ph++) {
            const __nv_bfloat16* Ap = (ph == 1) ? AlS : AhS;
            const __nv_bfloat16* Vp = (ph == 2) ? VlS : VhS;
#pragma unroll
            for (int kc = 0; kc < 8; kc++) {
                wmma::fragment<wmma::matrix_a, 16, 16, 16, __nv_bfloat16, wmma::row_major> fa[4];
                wmma::fragment<wmma::matrix_b, 16, 16, 16, __nv_bfloat16, wmma::col_major> fb[2];
#pragma unroll
                for (int i = 0; i < 4; i++)
                    wmma::load_matrix_sync(fa[i], &Ap[(wm * 64 + i * 16) * APAD + kc * 16], APAD);
#pragma unroll
                for (int j = 0; j < 2; j++)
                    wmma::load_matrix_sync(fb[j], &Vp[(wn * 32 + j * 16) * APAD + kc * 16], APAD);
#pragma unroll
                for (int i = 0; i < 4; i++)
#pragma unroll
                    for (int j = 0; j < 2; j++)
                        wmma::mma_sync(accC[i][j], fa[i], fb[j], accC[i][j]);
            }
        }
        __syncthreads();
    }

#pragma unroll
    for (int i = 0; i < 4; i++)
#pragma unroll
        for (int j = 0; j < 2; j++)
            wmma::store_matrix_sync(
                &Asm[(size_t)(wm * 64 + i * 16) * FPAD + wn * 32 + j * 16],
                accC[i][j], FPAD, wmma::mem_row_major);
    __syncthreads();
    {
        const int q = tid >> 1;
        const int hf = tid & 1;
        ushort hs[8], ls[8];
        size_t o = ((size_t)b << 20) + (size_t)(q0 + q) * 1024 + h * CC + hf * 64;
#pragma unroll
        for (int g = 0; g < 8; g++) {
#pragma unroll
            for (int j = 0; j < 8; j++) {
                float v = Asm[(size_t)q * FPAD + hf * 64 + g * 8 + j];
                __nv_bfloat16 hh = __float2bfloat16_rn(v);
                __nv_bfloat16 ll = __float2bfloat16_rn(v - __bfloat162float(hh));
                hs[j] = __bfloat16_as_ushort(hh);
                ls[j] = __bfloat16_as_ushort(ll);
            }
            *(uint4*)(cth + o + g * 8) =
                make_uint4((uint32_t)hs[0] | ((uint32_t)hs[1] << 16),
                           (uint32_t)hs[2] | ((uint32_t)hs[3] << 16),
                           (uint32_t)hs[4] | ((uint32_t)hs[5] << 16),
                           (uint32_t)hs[6] | ((uint32_t)hs[7] << 16));
            *(uint4*)(ctl + o + g * 8) =
                make_uint4((uint32_t)ls[0] | ((uint32_t)ls[1] << 16),
                           (uint32_t)ls[2] | ((uint32_t)ls[3] << 16),
                           (uint32_t)ls[4] | ((uint32_t)ls[5] << 16),
                           (uint32_t)ls[6] | ((uint32_t)ls[7] << 16));
        }
    }
}

// ---------------------------------------------------------------------------
// Launch
// ---------------------------------------------------------------------------
extern "C" void kernel_launch(void* const* d_in, const int* in_sizes, int n_in,
                              void* d_out, int out_size) {
    const float* x     = (const float*)d_in[0];
    const void*  maskr = d_in[1];
    const float* w_qkv = (const float*)d_in[2];
    const float* w_out = (const float*)d_in[3];
    float*       out   = (float*)d_out;

    void *p_coef, *p_mask;
    void *p_wqh, *p_wql, *p_woh, *p_wol, *p_xth, *p_xtl;
    void *p_qvh, *p_qvl, *p_cth, *p_ctl;
    cudaGetSymbolAddress(&p_coef, g_coef);
    cudaGetSymbolAddress(&p_mask, g_mask);
    cudaGetSymbolAddress(&p_wqh,  g_wq_h);
    cudaGetSymbolAddress(&p_wql,  g_wq_l);
    cudaGetSymbolAddress(&p_woh,  g_wo_h);
    cudaGetSymbolAddress(&p_wol,  g_wo_l);
    cudaGetSymbolAddress(&p_xth,  g_xt_h);
    cudaGetSymbolAddress(&p_xtl,  g_xt_l);
    cudaGetSymbolAddress(&p_qvh,  g_qkvh);
    cudaGetSymbolAddress(&p_qvl,  g_qkvl);
    cudaGetSymbolAddress(&p_cth,  g_ct_h);
    cudaGetSymbolAddress(&p_ctl,  g_ct_l);
    float* coef = (float*)p_coef;
    unsigned char* mask = (unsigned char*)p_mask;
    __nv_bfloat16* wqh = (__nv_bfloat16*)p_wqh;
    __nv_bfloat16* wql = (__nv_bfloat16*)p_wql;
    __nv_bfloat16* woh = (__nv_bfloat16*)p_woh;
    __nv_bfloat16* wol = (__nv_bfloat16*)p_wol;
    __nv_bfloat16* xth = (__nv_bfloat16*)p_xth;
    __nv_bfloat16* xtl = (__nv_bfloat16*)p_xtl;
    __nv_bfloat16* qvh = (__nv_bfloat16*)p_qvh;
    __nv_bfloat16* qvl = (__nv_bfloat16*)p_qvl;
    __nv_bfloat16* cth = (__nv_bfloat16*)p_cth;
    __nv_bfloat16* ctl = (__nv_bfloat16*)p_ctl;

    cudaFuncSetAttribute(attn_wmma, cudaFuncAttributeMaxDynamicSharedMemorySize,
                         ATTN_SMEM);

    // mask + coef
    detect_mask_kernel<<<1, 256>>>((const unsigned char*)maskr);
    normalize_mask_kernel<<<(int)(NMASK / 4 / 256), 256>>>(maskr, mask);
    coef_kernel<<<BB * SS, 256>>>(mask, coef);

    // operand prep
    conv_split_planar<<<3 * UU * UU / 8 / 256, 256>>>(w_qkv, wqh, wql, 3 * UU * UU);
    conv_split_planar<<<UU * UU / 8 / 256, 256>>>(w_out, woh, wol, UU * UU);
    conv_transpose_planar<<<dim3(32, 32, BB), dim3(32, 8)>>>(x, xth, xtl);

    // QKV projection with fused split epilogue -> qkv planes directly
    gemm_wmma<<<dim3(SS / 128, 3 * UU / 128, BB), 256>>>(
        wqh, wql, xth, xtl, nullptr, qvh, qvl, (size_t)3 * UU * SS);

    // WMMA attention -> ctx^T planes
    attn_wmma<<<dim3(SS / 128, HH, BB), 256, ATTN_SMEM>>>(
        qvh, qvl, mask, coef, cth, ctl);

    // output projection (fp32 epilogue -> d_out)
    gemm_wmma<<<dim3(SS / 128, UU / 128, BB), 256>>>(
        woh, wol, cth, ctl, out, nullptr, nullptr, (size_t)UU * SS);
}

// round 14
// speedup vs baseline: 1.0706x; 1.0259x over previous
#include <cuda_runtime.h>
#include <cuda_bf16.h>
#include <mma.h>
#include <cstdint>

using namespace nvcuda;

#define BB   16
#define UU   1024
#define HH   8
#define CC   128
#define SS   1024
#define SCALE 0.08838834764831843f   // 1/sqrt(128)

#define NMASK ((size_t)BB * SS * SS)

// ---------------------------------------------------------------------------
// Scratch
// ---------------------------------------------------------------------------
__device__ float g_coef[BB * SS];
__device__ unsigned char g_mask[NMASK];
__device__ int g_mode;
__device__ __nv_bfloat16 g_wq_h[(size_t)3 * UU * UU];
__device__ __nv_bfloat16 g_wq_l[(size_t)3 * UU * UU];
__device__ __nv_bfloat16 g_wo_h[(size_t)UU * UU];
__device__ __nv_bfloat16 g_wo_l[(size_t)UU * UU];
__device__ __nv_bfloat16 g_xt_h[(size_t)BB * UU * SS];
__device__ __nv_bfloat16 g_xt_l[(size_t)BB * UU * SS];
__device__ __nv_bfloat16 g_qkvh[(size_t)BB * 3 * UU * SS];
__device__ __nv_bfloat16 g_qkvl[(size_t)BB * 3 * UU * SS];
__device__ __nv_bfloat16 g_ct_h[(size_t)BB * UU * SS];
__device__ __nv_bfloat16 g_ct_l[(size_t)BB * UU * SS];

// ---------------------------------------------------------------------------
// cp.async helpers
// ---------------------------------------------------------------------------
__device__ __forceinline__ uint32_t smaddr(const void* p) {
    return (uint32_t)__cvta_generic_to_shared(p);
}
#define CP16(sm, gp) asm volatile("cp.async.cg.shared.global [%0], [%1], 16;" \
                                  :: "r"(sm), "l"(gp))
#define CP_COMMIT()  asm volatile("cp.async.commit_group;")
#define CP_WAIT1()   asm volatile("cp.async.wait_group 1;")
#define CP_WAIT0()   asm volatile("cp.async.wait_group 0;")

// ---------------------------------------------------------------------------
// Mask detect / normalize + coef (proven)
// ---------------------------------------------------------------------------
__global__ void detect_mask_kernel(const unsigned char* __restrict__ raw) {
    __shared__ int nz[4];
    if (threadIdx.x < 4) nz[threadIdx.x] = 0;
    __syncthreads();
    int c0 = 0, c1 = 0;
    for (int i = threadIdx.x * 4; i < (1 << 20); i += blockDim.x * 4) {
        uchar4 v = *(const uchar4*)(raw + i);
        c0 += (v.x != 0);
        c1 += (v.y != 0);
    }
    atomicAdd(&nz[0], c0);
    atomicAdd(&nz[1], c1);
    __syncthreads();
    if (threadIdx.x == 0)
        g_mode = (nz[1] > 0) ? 0 : (nz[0] > 0 ? 1 : 2);
}
__global__ void normalize_mask_kernel(const void* __restrict__ raw,
                                      unsigned char* __restrict__ dst) {
    size_t i = ((size_t)blockIdx.x * blockDim.x + threadIdx.x) * 4;
    if (i >= NMASK) return;
    int mode = g_mode;
    uchar4 o;
    if (mode == 0) {
        uchar4 v = *(const uchar4*)((const unsigned char*)raw + i);
        o = make_uchar4(v.x != 0, v.y != 0, v.z != 0, v.w != 0);
    } else if (mode == 1) {
        int4 v = *(const int4*)((const int*)raw + i);
        o = make_uchar4(v.x != 0, v.y != 0, v.z != 0, v.w != 0);
    } else {
        float4 v = *(const float4*)((const float*)raw + i);
        o = make_uchar4(v.x != 0.f, v.y != 0.f, v.z != 0.f, v.w != 0.f);
    }
    *(uchar4*)(dst + i) = o;
}
__global__ void coef_kernel(const unsigned char* __restrict__ mask,
                            float* __restrict__ coef) {
    int row = blockIdx.x;
    int tid = threadIdx.x;
    const uchar4 v = ((const uchar4*)(mask + (size_t)row * SS))[tid];
    int s = (int)v.x + (int)v.y + (int)v.z + (int)v.w;
#pragma unroll
    for (int o = 16; o; o >>= 1) s += __shfl_xor_sync(0xffffffffu, s, o);
    __shared__ int red[8];
    if ((tid & 31) == 0) red[tid >> 5] = s;
    __syncthreads();
    if (tid < 8) {
        int t = red[tid];
#pragma unroll
        for (int o = 4; o; o >>= 1) t += __shfl_xor_sync(0xffu, t, o);
        if (tid == 0) coef[row] = SCALE / (float)(t > 0 ? t : 1);
    }
}

// ---------------------------------------------------------------------------
// split fp32 -> hi/lo bf16 planes (weights)
// ---------------------------------------------------------------------------
__global__ void conv_split_planar(const float* __restrict__ src,
                                  __nv_bfloat16* __restrict__ dh,
                                  __nv_bfloat16* __restrict__ dl, int n) {
    int i0 = (blockIdx.x * blockDim.x + threadIdx.x) * 8;
    if (i0 >= n) return;
    ushort hs[8], ls[8];
#pragma unroll
    for (int j = 0; j < 8; j++) {
        float v = src[i0 + j];
        __nv_bfloat16 h = __float2bfloat16_rn(v);
        __nv_bfloat16 l = __float2bfloat16_rn(v - __bfloat162float(h));
        hs[j] = __bfloat16_as_ushort(h);
        ls[j] = __bfloat16_as_ushort(l);
    }
    *(uint4*)(dh + i0) = make_uint4((uint32_t)hs[0] | ((uint32_t)hs[1] << 16),
                                    (uint32_t)hs[2] | ((uint32_t)hs[3] << 16),
                                    (uint32_t)hs[4] | ((uint32_t)hs[5] << 16),
                                    (uint32_t)hs[6] | ((uint32_t)hs[7] << 16));
    *(uint4*)(dl + i0) = make_uint4((uint32_t)ls[0] | ((uint32_t)ls[1] << 16),
                                    (uint32_t)ls[2] | ((uint32_t)ls[3] << 16),
                                    (uint32_t)ls[4] | ((uint32_t)ls[5] << 16),
                                    (uint32_t)ls[6] | ((uint32_t)ls[7] << 16));
}

// ---------------------------------------------------------------------------
// transpose+split: [b][k][n] fp32 -> [b][n][k] bf16 planes (x)
// ---------------------------------------------------------------------------
__global__ void conv_transpose_planar(const float* __restrict__ src,
                                      __nv_bfloat16* __restrict__ dh,
                                      __nv_bfloat16* __restrict__ dl) {
    __shared__ float t[32][33];
    const int b = blockIdx.z;
    const int k0 = blockIdx.y * 32, n0 = blockIdx.x * 32;
    const float* s = src + ((size_t)b << 20);
    const int tx = threadIdx.x, ty = threadIdx.y;
#pragma unroll
    for (int j = 0; j < 32; j += 8)
        t[ty + j][tx] = s[(size_t)(k0 + ty + j) * 1024 + n0 + tx];
    __syncthreads();
    const int tid = ty * 32 + tx;
    const int nl = tid >> 3;
    const int kg = (tid & 7) * 4;
    ushort hs[4], ls[4];
#pragma unroll
    for (int i = 0; i < 4; i++) {
        float v = t[kg + i][nl];
        __nv_bfloat16 h = __float2bfloat16_rn(v);
        __nv_bfloat16 l = __float2bfloat16_rn(v - __bfloat162float(h));
        hs[i] = __bfloat16_as_ushort(h);
        ls[i] = __bfloat16_as_ushort(l);
    }
    size_t o = ((size_t)b << 20) + (size_t)(n0 + nl) * 1024 + k0 + kg;
    *(uint2*)(dh + o) = make_uint2((uint32_t)hs[0] | ((uint32_t)hs[1] << 16),
                                   (uint32_t)hs[2] | ((uint32_t)hs[3] << 16));
    *(uint2*)(dl + o) = make_uint2((uint32_t)ls[0] | ((uint32_t)ls[1] << 16),
                                   (uint32_t)ls[2] | ((uint32_t)ls[3] << 16));
}

// ---------------------------------------------------------------------------
// WMMA split-bf16 3-term GEMM (R12-proven, UNCHANGED): 128x128 CTA, warp
// 64x32, 2-stage cp.async. Epilogue: fp32 C, or fused split to Dh/Dl planes.
// ---------------------------------------------------------------------------
#define GBK 32
#define GPAD 40
#define GCHUNKS 96
#define EPAD 132

__global__ void __launch_bounds__(256, 2)
gemm_wmma(const __nv_bfloat16* __restrict__ Ah, const __nv_bfloat16* __restrict__ Al,
          const __nv_bfloat16* __restrict__ Bh, const __nv_bfloat16* __restrict__ Bl,
          float* __restrict__ C,
          __nv_bfloat16* __restrict__ Dh, __nv_bfloat16* __restrict__ Dl,
          size_t cStride) {
    __shared__ __align__(16) __nv_bfloat16 sbuf[2 * 2 * 128 * GPAD]; // 40960 B

    const int tid = threadIdx.x;
    const int wid = tid >> 5;
    const int wm = wid >> 2;
    const int wn = wid & 3;
    const int m0 = blockIdx.y * 128;
    const int n0 = blockIdx.x * 128;
    const size_t bOff = (size_t)blockIdx.z << 20;

    wmma::fragment<wmma::accumulator, 16, 16, 16, float> acc[4][2];
#pragma unroll
    for (int i = 0; i < 4; i++)
#pragma unroll
        for (int j = 0; j < 2; j++) wmma::fill_fragment(acc[i][j], 0.0f);

    auto stage = [&](int c, int buf) {
        const int phase = c >> 5;
        const int kk = (c & 31) * GBK;
        const __nv_bfloat16* Ap = (phase == 1) ? Al : Ah;
        const __nv_bfloat16* Bp = ((phase == 2) ? Bl : Bh) + bOff;
        __nv_bfloat16* As = sbuf + buf * (2 * 128 * GPAD);
        __nv_bfloat16* Bs = As + 128 * GPAD;
#pragma unroll
        for (int i = 0; i < 2; i++) {
            int idx = tid + i * 256;
            int r = idx >> 2, sg = (idx & 3) * 8;
            CP16(smaddr(As + r * GPAD + sg), Ap + (size_t)(m0 + r) * 1024 + kk + sg);
            CP16(smaddr(Bs + r * GPAD + sg), Bp + (size_t)(n0 + r) * 1024 + kk + sg);
        }
    };

    stage(0, 0);
    CP_COMMIT();

    for (int c = 0; c < GCHUNKS; ++c) {
        if (c + 1 < GCHUNKS) {
            stage(c + 1, (c + 1) & 1);
            CP_COMMIT();
            CP_WAIT1();
        } else {
            CP_WAIT0();
        }
        __syncthreads();
        const __nv_bfloat16* As = sbuf + (c & 1) * (2 * 128 * GPAD);
        const __nv_bfloat16* Bs = As + 128 * GPAD;
#pragma unroll
        for (int ks = 0; ks < 2; ks++) {
            wmma::fragment<wmma::matrix_a, 16, 16, 16, __nv_bfloat16, wmma::row_major> fa[4];
            wmma::fragment<wmma::matrix_b, 16, 16, 16, __nv_bfloat16, wmma::col_major> fb[2];
#pragma unroll
            for (int i = 0; i < 4; i++)
                wmma::load_matrix_sync(fa[i], As + (wm * 64 + i * 16) * GPAD + ks * 16, GPAD);
#pragma unroll
            for (int j = 0; j < 2; j++)
                wmma::load_matrix_sync(fb[j], Bs + (wn * 32 + j * 16) * GPAD + ks * 16, GPAD);
#pragma unroll
            for (int i = 0; i < 4; i++)
#pragma unroll
                for (int j = 0; j < 2; j++)
                    wmma::mma_sync(acc[i][j], fa[i], fb[j], acc[i][j]);
        }
        __syncthreads();
    }

    if (Dh == nullptr) {
        float* Cp = C + (size_t)blockIdx.z * cStride;
#pragma unroll
        for (int i = 0; i < 4; i++)
#pragma unroll
            for (int j = 0; j < 2; j++)
                wmma::store_matrix_sync(
                    Cp + (size_t)(m0 + wm * 64 + i * 16) * 1024 + n0 + wn * 32 + j * 16,
                    acc[i][j], 1024, wmma::mem_row_major);
    } else {
        float* esm = (float*)sbuf;
        __nv_bfloat16* dhp = Dh + (size_t)blockIdx.z * cStride;
        __nv_bfloat16* dlp = Dl + (size_t)blockIdx.z * cStride;
#pragma unroll
        for (int half = 0; half < 2; half++) {
            __syncthreads();
            if (wm == half) {
#pragma unroll
                for (int i = 0; i < 4; i++)
#pragma unroll
                    for (int j = 0; j < 2; j++)
                        wmma::store_matrix_sync(
                            &esm[(size_t)(i * 16) * EPAD + wn * 32 + j * 16],
                            acc[i][j], EPAD, wmma::mem_row_major);
            }
            __syncthreads();
            const int r = tid >> 2;
            const int cs = (tid & 3) * 32;
            size_t o = (size_t)(m0 + half * 64 + r) * 1024 + n0 + cs;
#pragma unroll
            for (int g = 0; g < 4; g++) {
                ushort hs[8], ls[8];
#pragma unroll
                for (int j = 0; j < 8; j++) {
                    float v = esm[(size_t)r * EPAD + cs + g * 8 + j];
                    __nv_bfloat16 hh = __float2bfloat16_rn(v);
                    __nv_bfloat16 ll = __float2bfloat16_rn(v - __bfloat162float(hh));
                    hs[j] = __bfloat16_as_ushort(hh);
                    ls[j] = __bfloat16_as_ushort(ll);
                }
                *(uint4*)(dhp + o + g * 8) =
                    make_uint4((uint32_t)hs[0] | ((uint32_t)hs[1] << 16),
                               (uint32_t)hs[2] | ((uint32_t)hs[3] << 16),
                               (uint32_t)hs[4] | ((uint32_t)hs[5] << 16),
                               (uint32_t)hs[6] | ((uint32_t)hs[7] << 16));
                *(uint4*)(dlp + o + g * 8) =
                    make_uint4((uint32_t)ls[0] | ((uint32_t)ls[1] << 16),
                               (uint32_t)ls[2] | ((uint32_t)ls[3] << 16),
                               (uint32_t)ls[4] | ((uint32_t)ls[5] << 16),
                               (uint32_t)ls[6] | ((uint32_t)ls[7] << 16));
            }
        }
    }
}

// ---------------------------------------------------------------------------
// WMMA attention with cp.async-pipelined QK^T staging.
// smem: AhS | AlS | B-region (V planes; aliased by fp32 scores AND the QK
// double-buffer, which are live at disjoint times) | coefs.
// ---------------------------------------------------------------------------
#define APAD 136
#define FPAD 132
#define OFF_AH 0
#define OFF_AL (128 * APAD * 2)                  // 34816
#define OFF_B  (OFF_AL + 128 * APAD * 2)         // 69632, region 69632 B
#define OFF_CF (OFF_B + 2 * 128 * APAD * 2)      // 139264
#define ATTN_SMEM (OFF_CF + 512)                 // 139776

__global__ void __launch_bounds__(256)
attn_wmma(const __nv_bfloat16* __restrict__ qh, const __nv_bfloat16* __restrict__ ql,
          const unsigned char* __restrict__ mask, const float* __restrict__ coef,
          __nv_bfloat16* __restrict__ cth, __nv_bfloat16* __restrict__ ctl) {
    extern __shared__ char sm[];
    __nv_bfloat16* AhS = (__nv_bfloat16*)(sm + OFF_AH);
    __nv_bfloat16* AlS = (__nv_bfloat16*)(sm + OFF_AL);
    float*         Asm = (float*)(sm + OFF_B);
    __nv_bfloat16* VhS = (__nv_bfloat16*)(sm + OFF_B);
    __nv_bfloat16* VlS = (__nv_bfloat16*)(sm + OFF_B + 128 * APAD * 2);
    __nv_bfloat16* Dbf = (__nv_bfloat16*)(sm + OFF_B);   // QK double-buffer alias
    float*         cfs = (float*)(sm + OFF_CF);

    const int q0 = blockIdx.x * 128;
    const int h  = blockIdx.y;
    const int b  = blockIdx.z;
    const int tid = threadIdx.x;
    const int wid = tid >> 5;
    const int wm = wid >> 2;
    const int wn = wid & 3;

    const size_t base = ((size_t)b * 3 * UU + (size_t)h * CC) * SS;
    const __nv_bfloat16* Qh = qh + base;
    const __nv_bfloat16* Ql = ql + base;
    const __nv_bfloat16* Kh = Qh + (size_t)UU * SS;
    const __nv_bfloat16* Kl = Ql + (size_t)UU * SS;
    const __nv_bfloat16* Vh = Qh + (size_t)2 * UU * SS;
    const __nv_bfloat16* Vl = Ql + (size_t)2 * UU * SS;
    const unsigned char* mg = mask + ((size_t)(b * SS + q0)) * SS;

    if (tid < 128) cfs[tid] = coef[b * SS + q0 + tid];

    wmma::fragment<wmma::accumulator, 16, 16, 16, float> accC[4][2];
#pragma unroll
    for (int i = 0; i < 4; i++)
#pragma unroll
        for (int j = 0; j < 2; j++) wmma::fill_fragment(accC[i][j], 0.0f);

    // cp.async stage of one (ph,cc) step: Q tile 32x128 + K tile 32x128
    auto stageQK = [&](int t, int k0, int buf) {
        const int ph = t >> 2;
        const int cc = t & 3;
        const __nv_bfloat16* Qp = (ph == 1) ? Ql : Qh;
        const __nv_bfloat16* Kp = (ph == 2) ? Kl : Kh;
        __nv_bfloat16* Qb = Dbf + buf * (2 * 32 * APAD);
        __nv_bfloat16* Kb = Qb + 32 * APAD;
#pragma unroll
        for (int i = 0; i < 2; i++) {
            int idx = tid + i * 256;          // 0..511
            int r = idx >> 4, sg = (idx & 15) * 8;
            CP16(smaddr(Qb + r * APAD + sg), Qp + (size_t)(cc * 32 + r) * SS + q0 + sg);
            CP16(smaddr(Kb + r * APAD + sg), Kp + (size_t)(cc * 32 + r) * SS + k0 + sg);
        }
    };

    for (int kt = 0; kt < 8; kt++) {
        const int k0 = kt * 128;

        // ---- QK^T (3-term), cp.async double-buffered over 12 steps ----
        wmma::fragment<wmma::accumulator, 16, 16, 16, float> accA[4][2];
#pragma unroll
        for (int i = 0; i < 4; i++)
#pragma unroll
            for (int j = 0; j < 2; j++) wmma::fill_fragment(accA[i][j], 0.0f);

        stageQK(0, k0, 0);
        CP_COMMIT();
        for (int t = 0; t < 12; t++) {
            if (t + 1 < 12) {
                stageQK(t + 1, k0, (t + 1) & 1);
                CP_COMMIT();
                CP_WAIT1();
            } else {
                CP_WAIT0();
            }
            __syncthreads();
            const __nv_bfloat16* Qb = Dbf + (t & 1) * (2 * 32 * APAD);
            const __nv_bfloat16* Kb = Qb + 32 * APAD;
#pragma unroll
            for (int ks = 0; ks < 2; ks++) {
                wmma::fragment<wmma::matrix_a, 16, 16, 16, __nv_bfloat16, wmma::col_major> fa[4];
                wmma::fragment<wmma::matrix_b, 16, 16, 16, __nv_bfloat16, wmma::row_major> fb[2];
#pragma unroll
                for (int i = 0; i < 4; i++)
                    wmma::load_matrix_sync(fa[i], &Qb[ks * 16 * APAD + wm * 64 + i * 16], APAD);
#pragma unroll
                for (int j = 0; j < 2; j++)
                    wmma::load_matrix_sync(fb[j], &Kb[ks * 16 * APAD + wn * 32 + j * 16], APAD);
#pragma unroll
                for (int i = 0; i < 4; i++)
#pragma unroll
                    for (int j = 0; j < 2; j++)
                        wmma::mma_sync(accA[i][j], fa[i], fb[j], accA[i][j]);
            }
            __syncthreads();
        }

        // ---- scores -> smem fp32 (double-buffer dead now) ----
#pragma unroll
        for (int i = 0; i < 4; i++)
#pragma unroll
            for (int j = 0; j < 2; j++)
                wmma::store_matrix_sync(
                    &Asm[(size_t)(wm * 64 + i * 16) * FPAD + wn * 32 + j * 16],
                    accA[i][j], FPAD, wmma::mem_row_major);
        __syncthreads();

        // ---- normalize + split ----
        {
            const int q = tid >> 1;
            const int hf = tid & 1;
            const float cf = cfs[q];
            const unsigned char* mrow = mg + (size_t)q * SS + k0 + hf * 64;
            uint4 mv[4];
#pragma unroll
            for (int i = 0; i < 4; i++) mv[i] = *(const uint4*)(mrow + i * 16);
            unsigned char mb[64];
            *(uint4*)(mb +  0) = mv[0];
            *(uint4*)(mb + 16) = mv[1];
            *(uint4*)(mb + 32) = mv[2];
            *(uint4*)(mb + 48) = mv[3];
            const int cbase = hf * 64;
#pragma unroll 16
            for (int j = 0; j < 64; j++) {
                float v = Asm[(size_t)q * FPAD + cbase + j];
                v = mb[j] ? fmaxf(v, 0.f) * cf : 0.f;
                __nv_bfloat16 hh = __float2bfloat16_rn(v);
                __nv_bfloat16 ll = __float2bfloat16_rn(v - __bfloat162float(hh));
                AhS[q * APAD + cbase + j] = hh;
                AlS[q * APAD + cbase + j] = ll;
            }
        }
        __syncthreads();   // Asm reads done -> V staging may overwrite region

        // ---- stage V tiles ----
#pragma unroll
        for (int it = 0; it < 16; it++) {
            int idx = tid + (it & 7) * 256;
            int r = idx >> 4, sg = (idx & 15) * 8;
            __nv_bfloat16* dst = (it < 8) ? VhS : VlS;
            const __nv_bfloat16* src = (it < 8) ? Vh : Vl;
            *(uint4*)&dst[r * APAD + sg] = *(const uint4*)(src + (size_t)r * SS + k0 + sg);
        }
        __syncthreads();

        // ---- A' V^T (3-term) ----
        for (int ph = 0; ph < 3; ph++) {
            const __nv_bfloat16* Ap = (ph == 1) ? AlS : AhS;
            const __nv_bfloat16* Vp = (ph == 2) ? VlS : VhS;
#pragma unroll
            for (int kc = 0; kc < 8; kc++) {
                wmma::fragment<wmma::matrix_a, 16, 16, 16, __nv_bfloat16, wmma::row_major> fa[4];
                wmma::fragment<wmma::matrix_b, 16, 16, 16, __nv_bfloat16, wmma::col_major> fb[2];
#pragma unroll
                for (int i = 0; i < 4; i++)
                    wmma::load_matrix_sync(fa[i], &Ap[(wm * 64 + i * 16) * APAD + kc * 16], APAD);
#pragma unroll
                for (int j = 0; j < 2; j++)
                    wmma::load_matrix_sync(fb[j], &Vp[(wn * 32 + j * 16) * APAD + kc * 16], APAD);
#pragma unroll
                for (int i = 0; i < 4; i++)
#pragma unroll
                    for (int j = 0; j < 2; j++)
                        wmma::mma_sync(accC[i][j], fa[i], fb[j], accC[i][j]);
            }
        }
        __syncthreads();   // V reads done before next kt's QK staging reuses region
    }

    // ---- epilogue: split planes ct[b][q0+q][h*128+c] ----
#pragma unroll
    for (int i = 0; i < 4; i++)
#pragma unroll
        for (int j = 0; j < 2; j++)
            wmma::store_matrix_sync(
                &Asm[(size_t)(wm * 64 + i * 16) * FPAD + wn * 32 + j * 16],
                accC[i][j], FPAD, wmma::mem_row_major);
    __syncthreads();
    {
        const int q = tid >> 1;
        const int hf = tid & 1;
        ushort hs[8], ls[8];
        size_t o = ((size_t)b << 20) + (size_t)(q0 + q) * 1024 + h * CC + hf * 64;
#pragma unroll
        for (int g = 0; g < 8; g++) {
#pragma unroll
            for (int j = 0; j < 8; j++) {
                float v = Asm[(size_t)q * FPAD + hf * 64 + g * 8 + j];
                __nv_bfloat16 hh = __float2bfloat16_rn(v);
                __nv_bfloat16 ll = __float2bfloat16_rn(v - __bfloat162float(hh));
                hs[j] = __bfloat16_as_ushort(hh);
                ls[j] = __bfloat16_as_ushort(ll);
            }
            *(uint4*)(cth + o + g * 8) =
                make_uint4((uint32_t)hs[0] | ((uint32_t)hs[1] << 16),
                           (uint32_t)hs[2] | ((uint32_t)hs[3] << 16),
                           (uint32_t)hs[4] | ((uint32_t)hs[5] << 16),
                           (uint32_t)hs[6] | ((uint32_t)hs[7] << 16));
            *(uint4*)(ctl + o + g * 8) =
                make_uint4((uint32_t)ls[0] | ((uint32_t)ls[1] << 16),
                           (uint32_t)ls[2] | ((uint32_t)ls[3] << 16),
                           (uint32_t)ls[4] | ((uint32_t)ls[5] << 16),
                           (uint32_t)ls[6] | ((uint32_t)ls[7] << 16));
        }
    }
}

// ---------------------------------------------------------------------------
// Launch
// ---------------------------------------------------------------------------
extern "C" void kernel_launch(void* const* d_in, const int* in_sizes, int n_in,
                              void* d_out, int out_size) {
    const float* x     = (const float*)d_in[0];
    const void*  maskr = d_in[1];
    const float* w_qkv = (const float*)d_in[2];
    const float* w_out = (const float*)d_in[3];
    float*       out   = (float*)d_out;

    void *p_coef, *p_mask;
    void *p_wqh, *p_wql, *p_woh, *p_wol, *p_xth, *p_xtl;
    void *p_qvh, *p_qvl, *p_cth, *p_ctl;
    cudaGetSymbolAddress(&p_coef, g_coef);
    cudaGetSymbolAddress(&p_mask, g_mask);
    cudaGetSymbolAddress(&p_wqh,  g_wq_h);
    cudaGetSymbolAddress(&p_wql,  g_wq_l);
    cudaGetSymbolAddress(&p_woh,  g_wo_h);
    cudaGetSymbolAddress(&p_wol,  g_wo_l);
    cudaGetSymbolAddress(&p_xth,  g_xt_h);
    cudaGetSymbolAddress(&p_xtl,  g_xt_l);
    cudaGetSymbolAddress(&p_qvh,  g_qkvh);
    cudaGetSymbolAddress(&p_qvl,  g_qkvl);
    cudaGetSymbolAddress(&p_cth,  g_ct_h);
    cudaGetSymbolAddress(&p_ctl,  g_ct_l);
    float* coef = (float*)p_coef;
    unsigned char* mask = (unsigned char*)p_mask;
    __nv_bfloat16* wqh = (__nv_bfloat16*)p_wqh;
    __nv_bfloat16* wql = (__nv_bfloat16*)p_wql;
    __nv_bfloat16* woh = (__nv_bfloat16*)p_woh;
    __nv_bfloat16* wol = (__nv_bfloat16*)p_wol;
    __nv_bfloat16* xth = (__nv_bfloat16*)p_xth;
    __nv_bfloat16* xtl = (__nv_bfloat16*)p_xtl;
    __nv_bfloat16* qvh = (__nv_bfloat16*)p_qvh;
    __nv_bfloat16* qvl = (__nv_bfloat16*)p_qvl;
    __nv_bfloat16* cth = (__nv_bfloat16*)p_cth;
    __nv_bfloat16* ctl = (__nv_bfloat16*)p_ctl;

    cudaFuncSetAttribute(attn_wmma, cudaFuncAttributeMaxDynamicSharedMemorySize,
                         ATTN_SMEM);

    // mask + coef
    detect_mask_kernel<<<1, 256>>>((const unsigned char*)maskr);
    normalize_mask_kernel<<<(int)(NMASK / 4 / 256), 256>>>(maskr, mask);
    coef_kernel<<<BB * SS, 256>>>(mask, coef);

    // operand prep
    conv_split_planar<<<3 * UU * UU / 8 / 256, 256>>>(w_qkv, wqh, wql, 3 * UU * UU);
    conv_split_planar<<<UU * UU / 8 / 256, 256>>>(w_out, woh, wol, UU * UU);
    conv_transpose_planar<<<dim3(32, 32, BB), dim3(32, 8)>>>(x, xth, xtl);

    // QKV projection with fused split epilogue -> qkv planes directly
    gemm_wmma<<<dim3(SS / 128, 3 * UU / 128, BB), 256>>>(
        wqh, wql, xth, xtl, nullptr, qvh, qvl, (size_t)3 * UU * SS);

    // WMMA attention (cp.async staging) -> ctx^T planes
    attn_wmma<<<dim3(SS / 128, HH, BB), 256, ATTN_SMEM>>>(
        qvh, qvl, mask, coef, cth, ctl);

    // output projection (fp32 epilogue -> d_out)
    gemm_wmma<<<dim3(SS / 128, UU / 128, BB), 256>>>(
        woh, wol, cth, ctl, out, nullptr, nullptr, (size_t)UU * SS);
}